// round 13
// baseline (speedup 1.0000x reference)
#include <cuda_runtime.h>
#include <cuda_fp16.h>

#define B    4
#define CIN  3
#define COUT 16
#define H    256
#define W    256
#define K    5
#define PAD  2
#define NP   (H / 2)      // 128 pair-rows

// Intermediate as vertical row-pairs: g_midp[bo][p][col] = {y[2p][col], y[2p+1][col]}
__device__ __half2 g_midp[B * COUT * NP * W];   // 8 MB

// odd-parity pair {a.y, b.x}
__device__ __forceinline__ __half2 oddpair(__half2 a, __half2 b) {
    unsigned r = __byte_perm(*(unsigned*)&a, *(unsigned*)&b, 0x5432);
    return *(__half2*)&r;
}

// ---------------------------------------------------------------------------
// Dilation: tile 32x32, 512 threads. Warp-group wg=ty>>3 handles 8 channels;
// tyr=ty&7 handles 4 rows (2 even pairs). One shared tile fill, 16 warps/blk.
// ---------------------------------------------------------------------------
#define DT_W 32
#define DT_H 32
#define DXR 18          // even pair rows: tile_y-2 .. tile_y+33
#define DXC (DT_W + 4)  // 36 cols

__global__ __launch_bounds__(512) void dilate_kernel(const float* __restrict__ x,
                                                     const float* __restrict__ wd) {
    __shared__ __half2 xs2[CIN][DXR][DXC];      // even row pairs {x[2p], x[2p+1]}
    __shared__ __half2 wsh[COUT * CIN * K * K]; // {w, w} replicated

    const int b      = blockIdx.z;
    const int tile_y = blockIdx.y * DT_H;
    const int tile_x = blockIdx.x * DT_W;
    const int tid    = threadIdx.y * 32 + threadIdx.x;

    for (int i = tid; i < COUT * CIN * K * K; i += 512)
        wsh[i] = __float2half2_rn(wd[i]);

    // fill even pairs: pair k = rows {tile_y-2+2k, tile_y-1+2k}, clamped
    const int XN = CIN * DXR * DXC;
    for (int i = tid; i < XN; i += 512) {
        int c   = i / (DXR * DXC);
        int rem = i % (DXR * DXC);
        int k   = rem / DXC;
        int col = rem % DXC;
        int r0 = min(max(tile_y - 2 + 2 * k, 0), H - 1);
        int r1 = min(max(tile_y - 1 + 2 * k, 0), H - 1);
        int gj = min(max(tile_x + col - PAD, 0), W - 1);
        const float* xc = x + ((size_t)(b * CIN + c)) * H * W;
        xs2[c][k][col] = __floats2half2_rn(xc[r0 * W + gj], xc[r1 * W + gj]);
    }
    __syncthreads();

    const int tx  = threadIdx.x;
    const int wg  = threadIdx.y >> 3;           // 0/1 -> channel group
    const int tyr = threadIdx.y & 7;            // row group
    const int och = wg * 8;
    const int gj  = tile_x + tx;
    const int p0  = (tile_y >> 1) + tyr * 2;    // global pair of output pair A

    const __half2 NEGINF2 = __half2half2(__ushort_as_half((unsigned short)0xFC00));

    float aA0[8], aA1[8], aB0[8], aB1[8];
#pragma unroll
    for (int o = 0; o < 8; o++) { aA0[o] = aA1[o] = aB0[o] = aB1[o] = 0.0f; }

#pragma unroll
    for (int c = 0; c < CIN; c++) {
        __half2 mA[8], mB[8];
#pragma unroll
        for (int o = 0; o < 8; o++) { mA[o] = NEGINF2; mB[o] = NEGINF2; }

#pragma unroll
        for (int dj = 0; dj < K; dj++) {
            __half2 E0 = xs2[c][tyr * 2 + 0][tx + dj];
            __half2 E1 = xs2[c][tyr * 2 + 1][tx + dj];
            __half2 E2 = xs2[c][tyr * 2 + 2][tx + dj];
            __half2 E3 = xs2[c][tyr * 2 + 3][tx + dj];
            __half2 O0 = oddpair(E0, E1);
            __half2 O1 = oddpair(E1, E2);
            __half2 O2 = oddpair(E2, E3);

#pragma unroll
            for (int o = 0; o < 8; o++) {
                const __half2* w = &wsh[((och + o) * CIN + c) * (K * K) + dj];
                __half2 w0 = w[0];
                __half2 w1 = w[K];
                __half2 w2 = w[2 * K];
                __half2 w3 = w[3 * K];
                __half2 w4 = w[4 * K];
                // pair A (rows gr0, gr0+1)
                mA[o] = __hmax2(mA[o], __hadd2(E0, w0));
                mA[o] = __hmax2(mA[o], __hadd2(O0, w1));
                mA[o] = __hmax2(mA[o], __hadd2(E1, w2));
                mA[o] = __hmax2(mA[o], __hadd2(O1, w3));
                mA[o] = __hmax2(mA[o], __hadd2(E2, w4));
                // pair B (rows gr0+2, gr0+3)
                mB[o] = __hmax2(mB[o], __hadd2(E1, w0));
                mB[o] = __hmax2(mB[o], __hadd2(O1, w1));
                mB[o] = __hmax2(mB[o], __hadd2(E2, w2));
                mB[o] = __hmax2(mB[o], __hadd2(O2, w3));
                mB[o] = __hmax2(mB[o], __hadd2(E3, w4));
            }
        }

#pragma unroll
        for (int o = 0; o < 8; o++) {
            float2 fA = __half22float2(mA[o]);
            float2 fB = __half22float2(mB[o]);
            aA0[o] += fA.x; aA1[o] += fA.y;
            aB0[o] += fB.x; aB1[o] += fB.y;
        }
    }

#pragma unroll
    for (int o = 0; o < 8; o++) {
        __half2* dst = &g_midp[((b * COUT + och + o) * NP + p0) * W + gj];
        dst[0] = __floats2half2_rn(aA0[o], aA1[o]);
        dst[W] = __floats2half2_rn(aB0[o], aB1[o]);
    }
}

// ---------------------------------------------------------------------------
// Erosion: tile 64x64, 512 threads, each thread 8 rows x 1 col.
// cg = ty>>3 selects column half; tyr = ty&7 selects row group.
// ---------------------------------------------------------------------------
#define ER_TW 64
#define ER_TH 64
#define EP_R  34
#define EP_C  68

__global__ __launch_bounds__(512) void erode_kernel(const float* __restrict__ we_g,
                                                    float* __restrict__ out) {
    __shared__ __half2 ysp[EP_R][EP_C];
    __shared__ __half2 we2[K * K];          // {-w, -w}

    const int bo     = blockIdx.z;
    const int o      = bo % COUT;
    const int tile_y = blockIdx.y * ER_TH;
    const int tile_x = blockIdx.x * ER_TW;
    const int tx     = threadIdx.x;
    const int ty     = threadIdx.y;
    const int tid    = ty * 32 + tx;

    if (tid < K * K) {
        float w = we_g[o * K * K + tid];
        we2[tid] = __float2half2_rn(-w);
    }

    const __half2* yp = g_midp + (size_t)bo * NP * W;

    {
        const int gj0 = min(max(tile_x + tx - 2, 0), W - 1);        // cols 0..31
        const int gj1 = min(tile_x + tx + 30, W - 1);               // cols 32..63
        const int gj2 = min(tile_x + tx + 62, W - 1);               // cols 64..67 (tx<4)
        const int Pbase = (tile_y >> 1) - 1;
        for (int k = ty; k < EP_R; k += 16) {
            int Pr = Pbase + k;
            int P  = min(max(Pr, 0), NP - 1);
            bool lo = (Pr < 0), hi = (Pr > NP - 1);

            __half2 v0 = yp[P * W + gj0];
            if (lo) v0 = __half2half2(__low2half(v0));
            if (hi) v0 = __half2half2(__high2half(v0));
            ysp[k][tx] = v0;

            __half2 v1 = yp[P * W + gj1];
            if (lo) v1 = __half2half2(__low2half(v1));
            if (hi) v1 = __half2half2(__high2half(v1));
            ysp[k][32 + tx] = v1;

            if (tx < 4) {
                __half2 v2 = yp[P * W + gj2];
                if (lo) v2 = __half2half2(__low2half(v2));
                if (hi) v2 = __half2half2(__high2half(v2));
                ysp[k][64 + tx] = v2;
            }
        }
    }
    __syncthreads();

    const int cg  = ty >> 3;            // column half
    const int tyr = ty & 7;             // row group
    const int lc  = cg * 32 + tx;       // local column 0..63
    const int pw  = tyr * 4;

    const __half2 INF2 = __half2half2(__ushort_as_half((unsigned short)0x7C00));
    __half2 m0 = INF2, m1 = INF2, m2 = INF2, m3 = INF2;

#pragma unroll
    for (int dj = 0; dj < K; dj++) {
        __half2 E0 = ysp[pw + 0][lc + dj];
        __half2 E1 = ysp[pw + 1][lc + dj];
        __half2 E2 = ysp[pw + 2][lc + dj];
        __half2 E3 = ysp[pw + 3][lc + dj];
        __half2 E4 = ysp[pw + 4][lc + dj];
        __half2 E5 = ysp[pw + 5][lc + dj];
        __half2 O0 = oddpair(E0, E1);
        __half2 O1 = oddpair(E1, E2);
        __half2 O2 = oddpair(E2, E3);
        __half2 O3 = oddpair(E3, E4);
        __half2 O4 = oddpair(E4, E5);

        __half2 w;
        w  = we2[0 * K + dj];
        m0 = __hmin2(m0, __hadd2(E0, w));
        m1 = __hmin2(m1, __hadd2(E1, w));
        m2 = __hmin2(m2, __hadd2(E2, w));
        m3 = __hmin2(m3, __hadd2(E3, w));
        w  = we2[1 * K + dj];
        m0 = __hmin2(m0, __hadd2(O0, w));
        m1 = __hmin2(m1, __hadd2(O1, w));
        m2 = __hmin2(m2, __hadd2(O2, w));
        m3 = __hmin2(m3, __hadd2(O3, w));
        w  = we2[2 * K + dj];
        m0 = __hmin2(m0, __hadd2(E1, w));
        m1 = __hmin2(m1, __hadd2(E2, w));
        m2 = __hmin2(m2, __hadd2(E3, w));
        m3 = __hmin2(m3, __hadd2(E4, w));
        w  = we2[3 * K + dj];
        m0 = __hmin2(m0, __hadd2(O1, w));
        m1 = __hmin2(m1, __hadd2(O2, w));
        m2 = __hmin2(m2, __hadd2(O3, w));
        m3 = __hmin2(m3, __hadd2(O4, w));
        w  = we2[4 * K + dj];
        m0 = __hmin2(m0, __hadd2(E2, w));
        m1 = __hmin2(m1, __hadd2(E3, w));
        m2 = __hmin2(m2, __hadd2(E4, w));
        m3 = __hmin2(m3, __hadd2(E5, w));
    }

    const int gi = tile_y + tyr * 8;
    float* op = out + ((size_t)bo * H + gi) * W + tile_x + lc;
    float2 r;
    r = __half22float2(m0); op[0 * W] = r.x; op[1 * W] = r.y;
    r = __half22float2(m1); op[2 * W] = r.x; op[3 * W] = r.y;
    r = __half22float2(m2); op[4 * W] = r.x; op[5 * W] = r.y;
    r = __half22float2(m3); op[6 * W] = r.x; op[7 * W] = r.y;
}

// ---------------------------------------------------------------------------
extern "C" void kernel_launch(void* const* d_in, const int* in_sizes, int n_in,
                              void* d_out, int out_size) {
    const float* x  = (const float*)d_in[0];
    const float* wd = (const float*)d_in[1];
    const float* we = (const float*)d_in[2];
    float*       out = (float*)d_out;

    dim3 bD(32, 16);
    dim3 gD(W / DT_W, H / DT_H, B);          // 8 x 8 x 4 = 256 blocks x 512 thr
    dilate_kernel<<<gD, bD>>>(x, wd);

    dim3 bE(32, 16);
    dim3 gE(W / ER_TW, H / ER_TH, B * COUT); // 4 x 4 x 64 = 1024 blocks x 512 thr
    erode_kernel<<<gE, bE>>>(we, out);
}

// round 14
// speedup vs baseline: 2.5871x; 2.5871x over previous
#include <cuda_runtime.h>

#define B    4
#define CIN  3
#define COUT 16
#define H    256
#define W    256
#define K    5
#define PAD  2
#define NP   (H / 2)      // 128 pair-rows

// Scales: x,w_d at 4096; intermediate + w_e at 1024.
#define XSC   4096.0f
#define MIDSC 1024.0f
#define INVMID (1.0f / 1024.0f)

// Intermediate as vertical s16 row-pairs: {y[2p], y[2p+1]} @ scale 1024
__device__ unsigned g_midp[B * COUT * NP * W];   // 8 MB

// odd-parity pair {a.hi_of_low? no: {a.y, b.x}} at 16-bit granularity
__device__ __forceinline__ unsigned oddpair(unsigned a, unsigned b) {
    return __byte_perm(a, b, 0x5432);
}
__device__ __forceinline__ unsigned splat_lo(unsigned v) { return __byte_perm(v, v, 0x1010); }
__device__ __forceinline__ unsigned splat_hi(unsigned v) { return __byte_perm(v, v, 0x3232); }
__device__ __forceinline__ int lo16(unsigned v) { return ((int)(v << 16)) >> 16; }
__device__ __forceinline__ int hi16(unsigned v) { return ((int)v) >> 16; }
__device__ __forceinline__ unsigned pack16(int lo, int hi) {
    return (unsigned)(lo & 0xFFFF) | ((unsigned)hi << 16);
}

// ---------------------------------------------------------------------------
// Dilation: tile 32x32, 4 rows/thread (2 even pairs), 2 chunks of 8 channels.
// Fused add+max via __viaddmax_s16x2: 1 op per tap per row-pair.
// ---------------------------------------------------------------------------
#define DT_W 32
#define DT_H 32
#define DXR 18          // even pair rows: tile_y-2 .. tile_y+33
#define DXC (DT_W + 4)  // 36 cols

__global__ __launch_bounds__(256) void dilate_kernel(const float* __restrict__ x,
                                                     const float* __restrict__ wd) {
    __shared__ unsigned xs2[CIN][DXR][DXC];      // s16x2 row pairs @4096
    __shared__ unsigned wsh[COUT * CIN * K * K]; // {w, w} s16x2 @4096

    const int b      = blockIdx.z;
    const int tile_y = blockIdx.y * DT_H;
    const int tile_x = blockIdx.x * DT_W;
    const int tid    = threadIdx.y * 32 + threadIdx.x;

    for (int i = tid; i < COUT * CIN * K * K; i += 256) {
        int q = __float2int_rn(wd[i] * XSC);
        wsh[i] = (unsigned)(q & 0xFFFF) * 0x10001u;
    }

    const int XN = CIN * DXR * DXC;
    for (int i = tid; i < XN; i += 256) {
        int c   = i / (DXR * DXC);
        int rem = i % (DXR * DXC);
        int k   = rem / DXC;
        int col = rem % DXC;
        int r0 = min(max(tile_y - 2 + 2 * k, 0), H - 1);
        int r1 = min(max(tile_y - 1 + 2 * k, 0), H - 1);
        int gj = min(max(tile_x + col - PAD, 0), W - 1);
        const float* xc = x + ((size_t)(b * CIN + c)) * H * W;
        int q0 = __float2int_rn(xc[r0 * W + gj] * XSC);
        int q1 = __float2int_rn(xc[r1 * W + gj] * XSC);
        xs2[c][k][col] = pack16(q0, q1);
    }
    __syncthreads();

    const int tx = threadIdx.x;
    const int ty = threadIdx.y;
    const int gj = tile_x + tx;
    const int p0 = (tile_y >> 1) + ty * 2;      // global pair of output pair A

#pragma unroll
    for (int och = 0; och < COUT; och += 8) {
        int aA0[8], aA1[8], aB0[8], aB1[8];
#pragma unroll
        for (int o = 0; o < 8; o++) { aA0[o] = aA1[o] = aB0[o] = aB1[o] = 0; }

#pragma unroll
        for (int c = 0; c < CIN; c++) {
            unsigned mA[8], mB[8];
#pragma unroll
            for (int o = 0; o < 8; o++) { mA[o] = 0x80008000u; mB[o] = 0x80008000u; }

#pragma unroll
            for (int dj = 0; dj < K; dj++) {
                unsigned E0 = xs2[c][ty * 2 + 0][tx + dj];
                unsigned E1 = xs2[c][ty * 2 + 1][tx + dj];
                unsigned E2 = xs2[c][ty * 2 + 2][tx + dj];
                unsigned E3 = xs2[c][ty * 2 + 3][tx + dj];
                unsigned O0 = oddpair(E0, E1);
                unsigned O1 = oddpair(E1, E2);
                unsigned O2 = oddpair(E2, E3);

#pragma unroll
                for (int o = 0; o < 8; o++) {
                    const unsigned* w = &wsh[((och + o) * CIN + c) * (K * K) + dj];
                    unsigned w0 = w[0];
                    unsigned w1 = w[K];
                    unsigned w2 = w[2 * K];
                    unsigned w3 = w[3 * K];
                    unsigned w4 = w[4 * K];
                    // pair A (rows gr0, gr0+1)
                    mA[o] = __viaddmax_s16x2(E0, w0, mA[o]);
                    mA[o] = __viaddmax_s16x2(O0, w1, mA[o]);
                    mA[o] = __viaddmax_s16x2(E1, w2, mA[o]);
                    mA[o] = __viaddmax_s16x2(O1, w3, mA[o]);
                    mA[o] = __viaddmax_s16x2(E2, w4, mA[o]);
                    // pair B (rows gr0+2, gr0+3)
                    mB[o] = __viaddmax_s16x2(E1, w0, mB[o]);
                    mB[o] = __viaddmax_s16x2(O1, w1, mB[o]);
                    mB[o] = __viaddmax_s16x2(E2, w2, mB[o]);
                    mB[o] = __viaddmax_s16x2(O2, w3, mB[o]);
                    mB[o] = __viaddmax_s16x2(E3, w4, mB[o]);
                }
            }

#pragma unroll
            for (int o = 0; o < 8; o++) {
                aA0[o] += lo16(mA[o]); aA1[o] += hi16(mA[o]);
                aB0[o] += lo16(mB[o]); aB1[o] += hi16(mB[o]);
            }
        }

        // rescale 4096 -> 1024 (divide by 4, round) and pack
#pragma unroll
        for (int o = 0; o < 8; o++) {
            unsigned* dst = &g_midp[((b * COUT + och + o) * NP + p0) * W + gj];
            dst[0] = pack16((aA0[o] + 2) >> 2, (aA1[o] + 2) >> 2);
            dst[W] = pack16((aB0[o] + 2) >> 2, (aB1[o] + 2) >> 2);
        }
    }
}

// ---------------------------------------------------------------------------
// Erosion: out = min_t(y - w) exact in s16 @1024 via __viaddmin_s16x2.
// Tile 64x64, 8 rows x 2 cols per thread.
// ---------------------------------------------------------------------------
#define ER_TW 64
#define ER_TH 64
#define EP_R  34
#define EP_C  68

__global__ __launch_bounds__(256) void erode_kernel(const float* __restrict__ we_g,
                                                    float* __restrict__ out) {
    __shared__ unsigned ysp[EP_R][EP_C];
    __shared__ unsigned we2[K * K];          // {-w, -w} s16x2 @1024

    const int bo     = blockIdx.z;
    const int o      = bo % COUT;
    const int tile_y = blockIdx.y * ER_TH;
    const int tile_x = blockIdx.x * ER_TW;
    const int tx     = threadIdx.x;
    const int ty     = threadIdx.y;
    const int tid    = ty * 32 + tx;

    if (tid < K * K) {
        int q = __float2int_rn(-we_g[o * K * K + tid] * MIDSC);
        we2[tid] = (unsigned)(q & 0xFFFF) * 0x10001u;
    }

    const unsigned* yp = g_midp + (size_t)bo * NP * W;

    {
        const int gj0 = min(max(tile_x + tx - 2, 0), W - 1);        // cols 0..31
        const int gj1 = min(tile_x + tx + 30, W - 1);               // cols 32..63
        const int gj2 = min(tile_x + tx + 62, W - 1);               // cols 64..67 (tx<4)
        const int Pbase = (tile_y >> 1) - 1;
#pragma unroll
        for (int k = ty; k < EP_R; k += 8) {
            int Pr = Pbase + k;
            int P  = min(max(Pr, 0), NP - 1);
            bool lo = (Pr < 0), hi = (Pr > NP - 1);

            unsigned v0 = yp[P * W + gj0];
            if (lo) v0 = splat_lo(v0);
            if (hi) v0 = splat_hi(v0);
            ysp[k][tx] = v0;

            unsigned v1 = yp[P * W + gj1];
            if (lo) v1 = splat_lo(v1);
            if (hi) v1 = splat_hi(v1);
            ysp[k][32 + tx] = v1;

            if (tx < 4) {
                unsigned v2 = yp[P * W + gj2];
                if (lo) v2 = splat_lo(v2);
                if (hi) v2 = splat_hi(v2);
                ysp[k][64 + tx] = v2;
            }
        }
    }
    __syncthreads();

    const int pw = ty * 4;

#pragma unroll
    for (int cc = 0; cc < 2; cc++) {
        const int lc = tx + cc * 32;

        unsigned m0 = 0x7FFF7FFFu, m1 = m0, m2 = m0, m3 = m0;

#pragma unroll
        for (int dj = 0; dj < K; dj++) {
            unsigned E0 = ysp[pw + 0][lc + dj];
            unsigned E1 = ysp[pw + 1][lc + dj];
            unsigned E2 = ysp[pw + 2][lc + dj];
            unsigned E3 = ysp[pw + 3][lc + dj];
            unsigned E4 = ysp[pw + 4][lc + dj];
            unsigned E5 = ysp[pw + 5][lc + dj];
            unsigned O0 = oddpair(E0, E1);
            unsigned O1 = oddpair(E1, E2);
            unsigned O2 = oddpair(E2, E3);
            unsigned O3 = oddpair(E3, E4);
            unsigned O4 = oddpair(E4, E5);

            unsigned w;
            w  = we2[0 * K + dj];
            m0 = __viaddmin_s16x2(E0, w, m0);
            m1 = __viaddmin_s16x2(E1, w, m1);
            m2 = __viaddmin_s16x2(E2, w, m2);
            m3 = __viaddmin_s16x2(E3, w, m3);
            w  = we2[1 * K + dj];
            m0 = __viaddmin_s16x2(O0, w, m0);
            m1 = __viaddmin_s16x2(O1, w, m1);
            m2 = __viaddmin_s16x2(O2, w, m2);
            m3 = __viaddmin_s16x2(O3, w, m3);
            w  = we2[2 * K + dj];
            m0 = __viaddmin_s16x2(E1, w, m0);
            m1 = __viaddmin_s16x2(E2, w, m1);
            m2 = __viaddmin_s16x2(E3, w, m2);
            m3 = __viaddmin_s16x2(E4, w, m3);
            w  = we2[3 * K + dj];
            m0 = __viaddmin_s16x2(O1, w, m0);
            m1 = __viaddmin_s16x2(O2, w, m1);
            m2 = __viaddmin_s16x2(O3, w, m2);
            m3 = __viaddmin_s16x2(O4, w, m3);
            w  = we2[4 * K + dj];
            m0 = __viaddmin_s16x2(E2, w, m0);
            m1 = __viaddmin_s16x2(E3, w, m1);
            m2 = __viaddmin_s16x2(E4, w, m2);
            m3 = __viaddmin_s16x2(E5, w, m3);
        }

        const int gi = tile_y + ty * 8;
        float* op = out + ((size_t)bo * H + gi) * W + tile_x + lc;
        op[0 * W] = lo16(m0) * INVMID;
        op[1 * W] = hi16(m0) * INVMID;
        op[2 * W] = lo16(m1) * INVMID;
        op[3 * W] = hi16(m1) * INVMID;
        op[4 * W] = lo16(m2) * INVMID;
        op[5 * W] = hi16(m2) * INVMID;
        op[6 * W] = lo16(m3) * INVMID;
        op[7 * W] = hi16(m3) * INVMID;
    }
}

// ---------------------------------------------------------------------------
extern "C" void kernel_launch(void* const* d_in, const int* in_sizes, int n_in,
                              void* d_out, int out_size) {
    const float* x  = (const float*)d_in[0];
    const float* wd = (const float*)d_in[1];
    const float* we = (const float*)d_in[2];
    float*       out = (float*)d_out;

    dim3 bD(32, 8);
    dim3 gD(W / DT_W, H / DT_H, B);          // 8 x 8 x 4 = 256 blocks
    dilate_kernel<<<gD, bD>>>(x, wd);

    dim3 bE(32, 8);
    dim3 gE(W / ER_TW, H / ER_TH, B * COUT); // 4 x 4 x 64 = 1024 blocks
    erode_kernel<<<gE, bE>>>(we, out);
}

// round 15
// speedup vs baseline: 2.7569x; 1.0656x over previous
#include <cuda_runtime.h>

#define B    4
#define CIN  3
#define COUT 16
#define H    256
#define W    256
#define K    5
#define PAD  2
#define NP   (H / 2)      // 128 pair-rows

// Scales: x,w_d at 4096; intermediate + w_e at 1024.
#define XSC   4096.0f
#define MIDSC 1024.0f
#define INVMID (1.0f / 1024.0f)

// Intermediate as vertical s16 row-pairs: {y[2p], y[2p+1]} @ scale 1024
__device__ unsigned g_midp[B * COUT * NP * W];   // 8 MB

__device__ __forceinline__ unsigned oddpair(unsigned a, unsigned b) {
    return __byte_perm(a, b, 0x5432);
}
__device__ __forceinline__ unsigned splat_lo(unsigned v) { return __byte_perm(v, v, 0x1010); }
__device__ __forceinline__ unsigned splat_hi(unsigned v) { return __byte_perm(v, v, 0x3232); }
__device__ __forceinline__ int lo16(unsigned v) { return ((int)(v << 16)) >> 16; }
__device__ __forceinline__ int hi16(unsigned v) { return ((int)v) >> 16; }
__device__ __forceinline__ unsigned pack16(int lo, int hi) {
    return (unsigned)(lo & 0xFFFF) | ((unsigned)hi << 16);
}
__device__ __forceinline__ unsigned rep16(int q) {
    return (unsigned)(q & 0xFFFF) * 0x10001u;
}

// ---------------------------------------------------------------------------
// Dilation: tile 32x32, 4 rows/thread (2 even pairs), 2 chunks of 8 channels.
// Fused add+max via __viaddmax_s16x2. Weights laid out for LDS.128:
// wsh4[c][dj][o] = taps di=0..3, wsh1[c][dj][o] = tap di=4.
// ---------------------------------------------------------------------------
#define DT_W 32
#define DT_H 32
#define DXR 18          // even pair rows: tile_y-2 .. tile_y+33
#define DXC (DT_W + 4)  // 36 cols

__global__ __launch_bounds__(256) void dilate_kernel(const float* __restrict__ x,
                                                     const float* __restrict__ wd) {
    __shared__ unsigned xs2[CIN][DXR][DXC];     // s16x2 row pairs @4096
    __shared__ uint4    wsh4[CIN][K][COUT];     // di 0..3, replicated s16x2
    __shared__ unsigned wsh1[CIN][K][COUT];     // di 4

    const int b      = blockIdx.z;
    const int tile_y = blockIdx.y * DT_H;
    const int tile_x = blockIdx.x * DT_W;
    const int tid    = threadIdx.y * 32 + threadIdx.x;

    // weight prep: one thread per (c,dj,o) = 240 entries
    for (int i = tid; i < CIN * K * COUT; i += 256) {
        int o   = i % COUT;
        int rem = i / COUT;
        int dj  = rem % K;
        int c   = rem / K;
        const float* wp = wd + ((o * CIN + c) * K) * K + dj;
        uint4 v;
        v.x = rep16(__float2int_rn(wp[0 * K] * XSC));
        v.y = rep16(__float2int_rn(wp[1 * K] * XSC));
        v.z = rep16(__float2int_rn(wp[2 * K] * XSC));
        v.w = rep16(__float2int_rn(wp[3 * K] * XSC));
        wsh4[c][dj][o] = v;
        wsh1[c][dj][o] = rep16(__float2int_rn(wp[4 * K] * XSC));
    }

    const int XN = CIN * DXR * DXC;
    for (int i = tid; i < XN; i += 256) {
        int c   = i / (DXR * DXC);
        int rem = i % (DXR * DXC);
        int k   = rem / DXC;
        int col = rem % DXC;
        int r0 = min(max(tile_y - 2 + 2 * k, 0), H - 1);
        int r1 = min(max(tile_y - 1 + 2 * k, 0), H - 1);
        int gj = min(max(tile_x + col - PAD, 0), W - 1);
        const float* xc = x + ((size_t)(b * CIN + c)) * H * W;
        int q0 = __float2int_rn(xc[r0 * W + gj] * XSC);
        int q1 = __float2int_rn(xc[r1 * W + gj] * XSC);
        xs2[c][k][col] = pack16(q0, q1);
    }
    __syncthreads();

    const int tx = threadIdx.x;
    const int ty = threadIdx.y;
    const int gj = tile_x + tx;
    const int p0 = (tile_y >> 1) + ty * 2;      // global pair of output pair A

#pragma unroll
    for (int och = 0; och < COUT; och += 8) {
        int aA0[8], aA1[8], aB0[8], aB1[8];
#pragma unroll
        for (int o = 0; o < 8; o++) { aA0[o] = aA1[o] = aB0[o] = aB1[o] = 0; }

#pragma unroll
        for (int c = 0; c < CIN; c++) {
            unsigned mA[8], mB[8];
#pragma unroll
            for (int o = 0; o < 8; o++) { mA[o] = 0x80008000u; mB[o] = 0x80008000u; }

#pragma unroll
            for (int dj = 0; dj < K; dj++) {
                unsigned E0 = xs2[c][ty * 2 + 0][tx + dj];
                unsigned E1 = xs2[c][ty * 2 + 1][tx + dj];
                unsigned E2 = xs2[c][ty * 2 + 2][tx + dj];
                unsigned E3 = xs2[c][ty * 2 + 3][tx + dj];
                unsigned O0 = oddpair(E0, E1);
                unsigned O1 = oddpair(E1, E2);
                unsigned O2 = oddpair(E2, E3);

#pragma unroll
                for (int o = 0; o < 8; o++) {
                    uint4    w4 = wsh4[c][dj][och + o];
                    unsigned w5 = wsh1[c][dj][och + o];
                    // pair A (rows gr0, gr0+1)
                    mA[o] = __viaddmax_s16x2(E0, w4.x, mA[o]);
                    mA[o] = __viaddmax_s16x2(O0, w4.y, mA[o]);
                    mA[o] = __viaddmax_s16x2(E1, w4.z, mA[o]);
                    mA[o] = __viaddmax_s16x2(O1, w4.w, mA[o]);
                    mA[o] = __viaddmax_s16x2(E2, w5,   mA[o]);
                    // pair B (rows gr0+2, gr0+3)
                    mB[o] = __viaddmax_s16x2(E1, w4.x, mB[o]);
                    mB[o] = __viaddmax_s16x2(O1, w4.y, mB[o]);
                    mB[o] = __viaddmax_s16x2(E2, w4.z, mB[o]);
                    mB[o] = __viaddmax_s16x2(O2, w4.w, mB[o]);
                    mB[o] = __viaddmax_s16x2(E3, w5,   mB[o]);
                }
            }

#pragma unroll
            for (int o = 0; o < 8; o++) {
                aA0[o] += lo16(mA[o]); aA1[o] += hi16(mA[o]);
                aB0[o] += lo16(mB[o]); aB1[o] += hi16(mB[o]);
            }
        }

        // rescale 4096 -> 1024 (divide by 4, round) and pack
#pragma unroll
        for (int o = 0; o < 8; o++) {
            unsigned* dst = &g_midp[((b * COUT + och + o) * NP + p0) * W + gj];
            dst[0] = pack16((aA0[o] + 2) >> 2, (aA1[o] + 2) >> 2);
            dst[W] = pack16((aB0[o] + 2) >> 2, (aB1[o] + 2) >> 2);
        }
    }
}

// ---------------------------------------------------------------------------
// Erosion (unchanged, best measured): out = min_t(y - w) in s16 @1024.
// Tile 64x64, 8 rows x 2 cols per thread.
// ---------------------------------------------------------------------------
#define ER_TW 64
#define ER_TH 64
#define EP_R  34
#define EP_C  68

__global__ __launch_bounds__(256) void erode_kernel(const float* __restrict__ we_g,
                                                    float* __restrict__ out) {
    __shared__ unsigned ysp[EP_R][EP_C];
    __shared__ unsigned we2[K * K];          // {-w, -w} s16x2 @1024

    const int bo     = blockIdx.z;
    const int o      = bo % COUT;
    const int tile_y = blockIdx.y * ER_TH;
    const int tile_x = blockIdx.x * ER_TW;
    const int tx     = threadIdx.x;
    const int ty     = threadIdx.y;
    const int tid    = ty * 32 + tx;

    if (tid < K * K) {
        int q = __float2int_rn(-we_g[o * K * K + tid] * MIDSC);
        we2[tid] = rep16(q);
    }

    const unsigned* yp = g_midp + (size_t)bo * NP * W;

    {
        const int gj0 = min(max(tile_x + tx - 2, 0), W - 1);        // cols 0..31
        const int gj1 = min(tile_x + tx + 30, W - 1);               // cols 32..63
        const int gj2 = min(tile_x + tx + 62, W - 1);               // cols 64..67 (tx<4)
        const int Pbase = (tile_y >> 1) - 1;
#pragma unroll
        for (int k = ty; k < EP_R; k += 8) {
            int Pr = Pbase + k;
            int P  = min(max(Pr, 0), NP - 1);
            bool lo = (Pr < 0), hi = (Pr > NP - 1);

            unsigned v0 = yp[P * W + gj0];
            if (lo) v0 = splat_lo(v0);
            if (hi) v0 = splat_hi(v0);
            ysp[k][tx] = v0;

            unsigned v1 = yp[P * W + gj1];
            if (lo) v1 = splat_lo(v1);
            if (hi) v1 = splat_hi(v1);
            ysp[k][32 + tx] = v1;

            if (tx < 4) {
                unsigned v2 = yp[P * W + gj2];
                if (lo) v2 = splat_lo(v2);
                if (hi) v2 = splat_hi(v2);
                ysp[k][64 + tx] = v2;
            }
        }
    }
    __syncthreads();

    const int pw = ty * 4;

#pragma unroll
    for (int cc = 0; cc < 2; cc++) {
        const int lc = tx + cc * 32;

        unsigned m0 = 0x7FFF7FFFu, m1 = m0, m2 = m0, m3 = m0;

#pragma unroll
        for (int dj = 0; dj < K; dj++) {
            unsigned E0 = ysp[pw + 0][lc + dj];
            unsigned E1 = ysp[pw + 1][lc + dj];
            unsigned E2 = ysp[pw + 2][lc + dj];
            unsigned E3 = ysp[pw + 3][lc + dj];
            unsigned E4 = ysp[pw + 4][lc + dj];
            unsigned E5 = ysp[pw + 5][lc + dj];
            unsigned O0 = oddpair(E0, E1);
            unsigned O1 = oddpair(E1, E2);
            unsigned O2 = oddpair(E2, E3);
            unsigned O3 = oddpair(E3, E4);
            unsigned O4 = oddpair(E4, E5);

            unsigned w;
            w  = we2[0 * K + dj];
            m0 = __viaddmin_s16x2(E0, w, m0);
            m1 = __viaddmin_s16x2(E1, w, m1);
            m2 = __viaddmin_s16x2(E2, w, m2);
            m3 = __viaddmin_s16x2(E3, w, m3);
            w  = we2[1 * K + dj];
            m0 = __viaddmin_s16x2(O0, w, m0);
            m1 = __viaddmin_s16x2(O1, w, m1);
            m2 = __viaddmin_s16x2(O2, w, m2);
            m3 = __viaddmin_s16x2(O3, w, m3);
            w  = we2[2 * K + dj];
            m0 = __viaddmin_s16x2(E1, w, m0);
            m1 = __viaddmin_s16x2(E2, w, m1);
            m2 = __viaddmin_s16x2(E3, w, m2);
            m3 = __viaddmin_s16x2(E4, w, m3);
            w  = we2[3 * K + dj];
            m0 = __viaddmin_s16x2(O1, w, m0);
            m1 = __viaddmin_s16x2(O2, w, m1);
            m2 = __viaddmin_s16x2(O3, w, m2);
            m3 = __viaddmin_s16x2(O4, w, m3);
            w  = we2[4 * K + dj];
            m0 = __viaddmin_s16x2(E2, w, m0);
            m1 = __viaddmin_s16x2(E3, w, m1);
            m2 = __viaddmin_s16x2(E4, w, m2);
            m3 = __viaddmin_s16x2(E5, w, m3);
        }

        const int gi = tile_y + ty * 8;
        float* op = out + ((size_t)bo * H + gi) * W + tile_x + lc;
        op[0 * W] = lo16(m0) * INVMID;
        op[1 * W] = hi16(m0) * INVMID;
        op[2 * W] = lo16(m1) * INVMID;
        op[3 * W] = hi16(m1) * INVMID;
        op[4 * W] = lo16(m2) * INVMID;
        op[5 * W] = hi16(m2) * INVMID;
        op[6 * W] = lo16(m3) * INVMID;
        op[7 * W] = hi16(m3) * INVMID;
    }
}

// ---------------------------------------------------------------------------
extern "C" void kernel_launch(void* const* d_in, const int* in_sizes, int n_in,
                              void* d_out, int out_size) {
    const float* x  = (const float*)d_in[0];
    const float* wd = (const float*)d_in[1];
    const float* we = (const float*)d_in[2];
    float*       out = (float*)d_out;

    dim3 bD(32, 8);
    dim3 gD(W / DT_W, H / DT_H, B);          // 8 x 8 x 4 = 256 blocks
    dilate_kernel<<<gD, bD>>>(x, wd);

    dim3 bE(32, 8);
    dim3 gE(W / ER_TW, H / ER_TH, B * COUT); // 4 x 4 x 64 = 1024 blocks
    erode_kernel<<<gE, bE>>>(we, out);
}

// round 16
// speedup vs baseline: 2.9767x; 1.0797x over previous
#include <cuda_runtime.h>

#define B    4
#define CIN  3
#define COUT 16
#define H    256
#define W    256
#define K    5
#define PAD  2
#define NP   (H / 2)      // 128 pair-rows

// Everything at scale 1024: x, w_d, intermediate, w_e.
#define XSC   1024.0f
#define MIDSC 1024.0f
#define INVMID (1.0f / 1024.0f)

// Intermediate as vertical s16 row-pairs: {y[2p], y[2p+1]} @ scale 1024
__device__ unsigned g_midp[B * COUT * NP * W];   // 8 MB

__device__ __forceinline__ unsigned oddpair(unsigned a, unsigned b) {
    return __byte_perm(a, b, 0x5432);
}
__device__ __forceinline__ unsigned splat_lo(unsigned v) { return __byte_perm(v, v, 0x1010); }
__device__ __forceinline__ unsigned splat_hi(unsigned v) { return __byte_perm(v, v, 0x3232); }
__device__ __forceinline__ int lo16(unsigned v) { return ((int)(v << 16)) >> 16; }
__device__ __forceinline__ int hi16(unsigned v) { return ((int)v) >> 16; }
__device__ __forceinline__ unsigned pack16(int lo, int hi) {
    return (unsigned)(lo & 0xFFFF) | ((unsigned)hi << 16);
}
__device__ __forceinline__ unsigned rep16(int q) {
    return (unsigned)(q & 0xFFFF) * 0x10001u;
}

// ---------------------------------------------------------------------------
// Dilation: tile 32x32, 512 threads. wg=ty>>3 -> 8 channels, tyr=ty&7 -> 4
// rows (2 even pairs). Fused add+max (__viaddmax_s16x2), packed s16 accum
// (__vadd2), LDS.128 weights. Stores s16x2 pairs @1024 directly.
// ---------------------------------------------------------------------------
#define DT_W 32
#define DT_H 32
#define DXR 18          // even pair rows: tile_y-2 .. tile_y+33
#define DXC (DT_W + 4)  // 36 cols

__global__ __launch_bounds__(512) void dilate_kernel(const float* __restrict__ x,
                                                     const float* __restrict__ wd) {
    __shared__ unsigned xs2[CIN][DXR][DXC];     // s16x2 row pairs @1024
    __shared__ uint4    wsh4[CIN][K][COUT];     // taps di=0..3, replicated s16x2
    __shared__ unsigned wsh1[CIN][K][COUT];     // tap di=4

    const int b      = blockIdx.z;
    const int tile_y = blockIdx.y * DT_H;
    const int tile_x = blockIdx.x * DT_W;
    const int tid    = threadIdx.y * 32 + threadIdx.x;

    // weight prep: 240 (c,dj,o) entries
    if (tid < CIN * K * COUT) {
        int o   = tid % COUT;
        int rem = tid / COUT;
        int dj  = rem % K;
        int c   = rem / K;
        const float* wp = wd + ((o * CIN + c) * K) * K + dj;
        uint4 v;
        v.x = rep16(__float2int_rn(wp[0 * K] * XSC));
        v.y = rep16(__float2int_rn(wp[1 * K] * XSC));
        v.z = rep16(__float2int_rn(wp[2 * K] * XSC));
        v.w = rep16(__float2int_rn(wp[3 * K] * XSC));
        wsh4[c][dj][o] = v;
        wsh1[c][dj][o] = rep16(__float2int_rn(wp[4 * K] * XSC));
    }

    const int XN = CIN * DXR * DXC;   // 1944
    for (int i = tid; i < XN; i += 512) {
        int c   = i / (DXR * DXC);
        int rem = i % (DXR * DXC);
        int k   = rem / DXC;
        int col = rem % DXC;
        int r0 = min(max(tile_y - 2 + 2 * k, 0), H - 1);
        int r1 = min(max(tile_y - 1 + 2 * k, 0), H - 1);
        int gj = min(max(tile_x + col - PAD, 0), W - 1);
        const float* xc = x + ((size_t)(b * CIN + c)) * H * W;
        int q0 = __float2int_rn(xc[r0 * W + gj] * XSC);
        int q1 = __float2int_rn(xc[r1 * W + gj] * XSC);
        xs2[c][k][col] = pack16(q0, q1);
    }
    __syncthreads();

    const int tx  = threadIdx.x;
    const int wg  = threadIdx.y >> 3;           // channel group 0/1
    const int tyr = threadIdx.y & 7;            // row group
    const int och = wg * 8;
    const int gj  = tile_x + tx;
    const int p0  = (tile_y >> 1) + tyr * 2;    // global pair of output pair A

    unsigned pA[8], pB[8];                      // packed s16 accumulators
#pragma unroll
    for (int o = 0; o < 8; o++) { pA[o] = 0; pB[o] = 0; }

#pragma unroll
    for (int c = 0; c < CIN; c++) {
        unsigned mA[8], mB[8];
#pragma unroll
        for (int o = 0; o < 8; o++) { mA[o] = 0x80008000u; mB[o] = 0x80008000u; }

#pragma unroll
        for (int dj = 0; dj < K; dj++) {
            unsigned E0 = xs2[c][tyr * 2 + 0][tx + dj];
            unsigned E1 = xs2[c][tyr * 2 + 1][tx + dj];
            unsigned E2 = xs2[c][tyr * 2 + 2][tx + dj];
            unsigned E3 = xs2[c][tyr * 2 + 3][tx + dj];
            unsigned O0 = oddpair(E0, E1);
            unsigned O1 = oddpair(E1, E2);
            unsigned O2 = oddpair(E2, E3);

#pragma unroll
            for (int o = 0; o < 8; o++) {
                uint4    w4 = wsh4[c][dj][och + o];
                unsigned w5 = wsh1[c][dj][och + o];
                // pair A (rows gr0, gr0+1)
                mA[o] = __viaddmax_s16x2(E0, w4.x, mA[o]);
                mA[o] = __viaddmax_s16x2(O0, w4.y, mA[o]);
                mA[o] = __viaddmax_s16x2(E1, w4.z, mA[o]);
                mA[o] = __viaddmax_s16x2(O1, w4.w, mA[o]);
                mA[o] = __viaddmax_s16x2(E2, w5,   mA[o]);
                // pair B (rows gr0+2, gr0+3)
                mB[o] = __viaddmax_s16x2(E1, w4.x, mB[o]);
                mB[o] = __viaddmax_s16x2(O1, w4.y, mB[o]);
                mB[o] = __viaddmax_s16x2(E2, w4.z, mB[o]);
                mB[o] = __viaddmax_s16x2(O2, w4.w, mB[o]);
                mB[o] = __viaddmax_s16x2(E3, w5,   mB[o]);
            }
        }

#pragma unroll
        for (int o = 0; o < 8; o++) {
            pA[o] = __vadd2(pA[o], mA[o]);   // per-lane s16 add, no overflow (<=18.4K)
            pB[o] = __vadd2(pB[o], mB[o]);
        }
    }

#pragma unroll
    for (int o = 0; o < 8; o++) {
        unsigned* dst = &g_midp[((b * COUT + och + o) * NP + p0) * W + gj];
        dst[0] = pA[o];
        dst[W] = pB[o];
    }
}

// ---------------------------------------------------------------------------
// Erosion (unchanged, best measured): out = min_t(y - w) in s16 @1024.
// Tile 64x64, 8 rows x 2 cols per thread.
// ---------------------------------------------------------------------------
#define ER_TW 64
#define ER_TH 64
#define EP_R  34
#define EP_C  68

__global__ __launch_bounds__(256) void erode_kernel(const float* __restrict__ we_g,
                                                    float* __restrict__ out) {
    __shared__ unsigned ysp[EP_R][EP_C];
    __shared__ unsigned we2[K * K];          // {-w, -w} s16x2 @1024

    const int bo     = blockIdx.z;
    const int o      = bo % COUT;
    const int tile_y = blockIdx.y * ER_TH;
    const int tile_x = blockIdx.x * ER_TW;
    const int tx     = threadIdx.x;
    const int ty     = threadIdx.y;
    const int tid    = ty * 32 + tx;

    if (tid < K * K) {
        int q = __float2int_rn(-we_g[o * K * K + tid] * MIDSC);
        we2[tid] = rep16(q);
    }

    const unsigned* yp = g_midp + (size_t)bo * NP * W;

    {
        const int gj0 = min(max(tile_x + tx - 2, 0), W - 1);        // cols 0..31
        const int gj1 = min(tile_x + tx + 30, W - 1);               // cols 32..63
        const int gj2 = min(tile_x + tx + 62, W - 1);               // cols 64..67 (tx<4)
        const int Pbase = (tile_y >> 1) - 1;
#pragma unroll
        for (int k = ty; k < EP_R; k += 8) {
            int Pr = Pbase + k;
            int P  = min(max(Pr, 0), NP - 1);
            bool lo = (Pr < 0), hi = (Pr > NP - 1);

            unsigned v0 = yp[P * W + gj0];
            if (lo) v0 = splat_lo(v0);
            if (hi) v0 = splat_hi(v0);
            ysp[k][tx] = v0;

            unsigned v1 = yp[P * W + gj1];
            if (lo) v1 = splat_lo(v1);
            if (hi) v1 = splat_hi(v1);
            ysp[k][32 + tx] = v1;

            if (tx < 4) {
                unsigned v2 = yp[P * W + gj2];
                if (lo) v2 = splat_lo(v2);
                if (hi) v2 = splat_hi(v2);
                ysp[k][64 + tx] = v2;
            }
        }
    }
    __syncthreads();

    const int pw = ty * 4;

#pragma unroll
    for (int cc = 0; cc < 2; cc++) {
        const int lc = tx + cc * 32;

        unsigned m0 = 0x7FFF7FFFu, m1 = m0, m2 = m0, m3 = m0;

#pragma unroll
        for (int dj = 0; dj < K; dj++) {
            unsigned E0 = ysp[pw + 0][lc + dj];
            unsigned E1 = ysp[pw + 1][lc + dj];
            unsigned E2 = ysp[pw + 2][lc + dj];
            unsigned E3 = ysp[pw + 3][lc + dj];
            unsigned E4 = ysp[pw + 4][lc + dj];
            unsigned E5 = ysp[pw + 5][lc + dj];
            unsigned O0 = oddpair(E0, E1);
            unsigned O1 = oddpair(E1, E2);
            unsigned O2 = oddpair(E2, E3);
            unsigned O3 = oddpair(E3, E4);
            unsigned O4 = oddpair(E4, E5);

            unsigned w;
            w  = we2[0 * K + dj];
            m0 = __viaddmin_s16x2(E0, w, m0);
            m1 = __viaddmin_s16x2(E1, w, m1);
            m2 = __viaddmin_s16x2(E2, w, m2);
            m3 = __viaddmin_s16x2(E3, w, m3);
            w  = we2[1 * K + dj];
            m0 = __viaddmin_s16x2(O0, w, m0);
            m1 = __viaddmin_s16x2(O1, w, m1);
            m2 = __viaddmin_s16x2(O2, w, m2);
            m3 = __viaddmin_s16x2(O3, w, m3);
            w  = we2[2 * K + dj];
            m0 = __viaddmin_s16x2(E1, w, m0);
            m1 = __viaddmin_s16x2(E2, w, m1);
            m2 = __viaddmin_s16x2(E3, w, m2);
            m3 = __viaddmin_s16x2(E4, w, m3);
            w  = we2[3 * K + dj];
            m0 = __viaddmin_s16x2(O1, w, m0);
            m1 = __viaddmin_s16x2(O2, w, m1);
            m2 = __viaddmin_s16x2(O3, w, m2);
            m3 = __viaddmin_s16x2(O4, w, m3);
            w  = we2[4 * K + dj];
            m0 = __viaddmin_s16x2(E2, w, m0);
            m1 = __viaddmin_s16x2(E3, w, m1);
            m2 = __viaddmin_s16x2(E4, w, m2);
            m3 = __viaddmin_s16x2(E5, w, m3);
        }

        const int gi = tile_y + ty * 8;
        float* op = out + ((size_t)bo * H + gi) * W + tile_x + lc;
        op[0 * W] = lo16(m0) * INVMID;
        op[1 * W] = hi16(m0) * INVMID;
        op[2 * W] = lo16(m1) * INVMID;
        op[3 * W] = hi16(m1) * INVMID;
        op[4 * W] = lo16(m2) * INVMID;
        op[5 * W] = hi16(m2) * INVMID;
        op[6 * W] = lo16(m3) * INVMID;
        op[7 * W] = hi16(m3) * INVMID;
    }
}

// ---------------------------------------------------------------------------
extern "C" void kernel_launch(void* const* d_in, const int* in_sizes, int n_in,
                              void* d_out, int out_size) {
    const float* x  = (const float*)d_in[0];
    const float* wd = (const float*)d_in[1];
    const float* we = (const float*)d_in[2];
    float*       out = (float*)d_out;

    dim3 bD(32, 16);
    dim3 gD(W / DT_W, H / DT_H, B);          // 8 x 8 x 4 = 256 blocks x 512 thr
    dilate_kernel<<<gD, bD>>>(x, wd);

    dim3 bE(32, 8);
    dim3 gE(W / ER_TW, H / ER_TH, B * COUT); // 4 x 4 x 64 = 1024 blocks
    erode_kernel<<<gE, bE>>>(we, out);
}

// round 17
// speedup vs baseline: 2.9900x; 1.0044x over previous
#include <cuda_runtime.h>

#define B    4
#define CIN  3
#define COUT 16
#define H    256
#define W    256
#define K    5
#define PAD  2
#define NP   (H / 2)      // 128 pair-rows

// Everything at scale 1024: x, w_d, intermediate, w_e.
#define XSC   1024.0f
#define MIDSC 1024.0f
#define INVMID (1.0f / 1024.0f)

// Intermediate as vertical s16 row-pairs: {y[2p], y[2p+1]} @ scale 1024
__device__ unsigned g_midp[B * COUT * NP * W];   // 8 MB

__device__ __forceinline__ unsigned oddpair(unsigned a, unsigned b) {
    return __byte_perm(a, b, 0x5432);
}
__device__ __forceinline__ unsigned splat_lo(unsigned v) { return __byte_perm(v, v, 0x1010); }
__device__ __forceinline__ unsigned splat_hi(unsigned v) { return __byte_perm(v, v, 0x3232); }
__device__ __forceinline__ int lo16(unsigned v) { return ((int)(v << 16)) >> 16; }
__device__ __forceinline__ int hi16(unsigned v) { return ((int)v) >> 16; }
__device__ __forceinline__ unsigned pack16(int lo, int hi) {
    return (unsigned)(lo & 0xFFFF) | ((unsigned)hi << 16);
}
__device__ __forceinline__ unsigned rep16(int q) {
    return (unsigned)(q & 0xFFFF) * 0x10001u;
}

// ---------------------------------------------------------------------------
// Dilation (unchanged from R16 best): tile 32x32, 512 threads, wg=ty>>3 ->
// 8 channels, tyr=ty&7 -> 4 rows. viaddmax + packed s16 accum + LDS.128 w.
// ---------------------------------------------------------------------------
#define DT_W 32
#define DT_H 32
#define DXR 18
#define DXC (DT_W + 4)

__global__ __launch_bounds__(512) void dilate_kernel(const float* __restrict__ x,
                                                     const float* __restrict__ wd) {
    __shared__ unsigned xs2[CIN][DXR][DXC];
    __shared__ uint4    wsh4[CIN][K][COUT];
    __shared__ unsigned wsh1[CIN][K][COUT];

    const int b      = blockIdx.z;
    const int tile_y = blockIdx.y * DT_H;
    const int tile_x = blockIdx.x * DT_W;
    const int tid    = threadIdx.y * 32 + threadIdx.x;

    if (tid < CIN * K * COUT) {
        int o   = tid % COUT;
        int rem = tid / COUT;
        int dj  = rem % K;
        int c   = rem / K;
        const float* wp = wd + ((o * CIN + c) * K) * K + dj;
        uint4 v;
        v.x = rep16(__float2int_rn(wp[0 * K] * XSC));
        v.y = rep16(__float2int_rn(wp[1 * K] * XSC));
        v.z = rep16(__float2int_rn(wp[2 * K] * XSC));
        v.w = rep16(__float2int_rn(wp[3 * K] * XSC));
        wsh4[c][dj][o] = v;
        wsh1[c][dj][o] = rep16(__float2int_rn(wp[4 * K] * XSC));
    }

    const int XN = CIN * DXR * DXC;
    for (int i = tid; i < XN; i += 512) {
        int c   = i / (DXR * DXC);
        int rem = i % (DXR * DXC);
        int k   = rem / DXC;
        int col = rem % DXC;
        int r0 = min(max(tile_y - 2 + 2 * k, 0), H - 1);
        int r1 = min(max(tile_y - 1 + 2 * k, 0), H - 1);
        int gj = min(max(tile_x + col - PAD, 0), W - 1);
        const float* xc = x + ((size_t)(b * CIN + c)) * H * W;
        int q0 = __float2int_rn(xc[r0 * W + gj] * XSC);
        int q1 = __float2int_rn(xc[r1 * W + gj] * XSC);
        xs2[c][k][col] = pack16(q0, q1);
    }
    __syncthreads();

    const int tx  = threadIdx.x;
    const int wg  = threadIdx.y >> 3;
    const int tyr = threadIdx.y & 7;
    const int och = wg * 8;
    const int gj  = tile_x + tx;
    const int p0  = (tile_y >> 1) + tyr * 2;

    unsigned pA[8], pB[8];
#pragma unroll
    for (int o = 0; o < 8; o++) { pA[o] = 0; pB[o] = 0; }

#pragma unroll
    for (int c = 0; c < CIN; c++) {
        unsigned mA[8], mB[8];
#pragma unroll
        for (int o = 0; o < 8; o++) { mA[o] = 0x80008000u; mB[o] = 0x80008000u; }

#pragma unroll
        for (int dj = 0; dj < K; dj++) {
            unsigned E0 = xs2[c][tyr * 2 + 0][tx + dj];
            unsigned E1 = xs2[c][tyr * 2 + 1][tx + dj];
            unsigned E2 = xs2[c][tyr * 2 + 2][tx + dj];
            unsigned E3 = xs2[c][tyr * 2 + 3][tx + dj];
            unsigned O0 = oddpair(E0, E1);
            unsigned O1 = oddpair(E1, E2);
            unsigned O2 = oddpair(E2, E3);

#pragma unroll
            for (int o = 0; o < 8; o++) {
                uint4    w4 = wsh4[c][dj][och + o];
                unsigned w5 = wsh1[c][dj][och + o];
                mA[o] = __viaddmax_s16x2(E0, w4.x, mA[o]);
                mA[o] = __viaddmax_s16x2(O0, w4.y, mA[o]);
                mA[o] = __viaddmax_s16x2(E1, w4.z, mA[o]);
                mA[o] = __viaddmax_s16x2(O1, w4.w, mA[o]);
                mA[o] = __viaddmax_s16x2(E2, w5,   mA[o]);
                mB[o] = __viaddmax_s16x2(E1, w4.x, mB[o]);
                mB[o] = __viaddmax_s16x2(O1, w4.y, mB[o]);
                mB[o] = __viaddmax_s16x2(E2, w4.z, mB[o]);
                mB[o] = __viaddmax_s16x2(O2, w4.w, mB[o]);
                mB[o] = __viaddmax_s16x2(E3, w5,   mB[o]);
            }
        }

#pragma unroll
        for (int o = 0; o < 8; o++) {
            pA[o] = __vadd2(pA[o], mA[o]);
            pB[o] = __vadd2(pB[o], mB[o]);
        }
    }

#pragma unroll
    for (int o = 0; o < 8; o++) {
        unsigned* dst = &g_midp[((b * COUT + och + o) * NP + p0) * W + gj];
        dst[0] = pA[o];
        dst[W] = pB[o];
    }
}

// ---------------------------------------------------------------------------
// Erosion: tile 64x64, 8 rows x 2 cols per thread. Transposed smem
// yt[col][pair] -> E0..E5 via 1 LDS.128 + 1 LDS.64. Weights in registers.
// ---------------------------------------------------------------------------
#define ER_TW 64
#define ER_TH 64
#define ET_C  68     // cols
#define ET_P  36     // pair dim padded (34 used) - keeps 16B alignment

__global__ __launch_bounds__(256) void erode_kernel(const float* __restrict__ we_g,
                                                    float* __restrict__ out) {
    __shared__ unsigned yt[ET_C][ET_P];      // [col][pair]
    __shared__ unsigned we2[32];             // {-w,-w} s16x2 @1024 (25 used)

    const int bo     = blockIdx.z;
    const int o      = bo % COUT;
    const int tile_y = blockIdx.y * ER_TH;
    const int tile_x = blockIdx.x * ER_TW;
    const int tx     = threadIdx.x;
    const int ty     = threadIdx.y;
    const int tid    = ty * 32 + tx;

    if (tid < K * K) {
        int q = __float2int_rn(-we_g[o * K * K + tid] * MIDSC);
        we2[tid] = rep16(q);
    }

    const unsigned* yp = g_midp + (size_t)bo * NP * W;

    {
        const int gj0 = min(max(tile_x + tx - 2, 0), W - 1);        // cols 0..31
        const int gj1 = min(tile_x + tx + 30, W - 1);               // cols 32..63
        const int gj2 = min(tile_x + tx + 62, W - 1);               // cols 64..67 (tx<4)
        const int Pbase = (tile_y >> 1) - 1;
#pragma unroll
        for (int k = ty; k < 34; k += 8) {
            int Pr = Pbase + k;
            int P  = min(max(Pr, 0), NP - 1);
            bool lo = (Pr < 0), hi = (Pr > NP - 1);

            unsigned v0 = yp[P * W + gj0];
            if (lo) v0 = splat_lo(v0);
            if (hi) v0 = splat_hi(v0);
            yt[tx][k] = v0;

            unsigned v1 = yp[P * W + gj1];
            if (lo) v1 = splat_lo(v1);
            if (hi) v1 = splat_hi(v1);
            yt[32 + tx][k] = v1;

            if (tx < 4) {
                unsigned v2 = yp[P * W + gj2];
                if (lo) v2 = splat_lo(v2);
                if (hi) v2 = splat_hi(v2);
                yt[64 + tx][k] = v2;
            }
        }
    }
    __syncthreads();

    // all 25 weights into registers (broadcast loads, once)
    unsigned wr[25];
#pragma unroll
    for (int t = 0; t < 25; t++) wr[t] = we2[t];

    const int pw = ty * 4;

#pragma unroll
    for (int cc = 0; cc < 2; cc++) {
        const int lc = tx + cc * 32;

        unsigned m0 = 0x7FFF7FFFu, m1 = m0, m2 = m0, m3 = m0;

#pragma unroll
        for (int dj = 0; dj < K; dj++) {
            const unsigned* colp = &yt[lc + dj][pw];
            uint4 e0123 = *reinterpret_cast<const uint4*>(colp);      // E0..E3
            uint2 e45   = *reinterpret_cast<const uint2*>(colp + 4);  // E4,E5
            unsigned E0 = e0123.x, E1 = e0123.y, E2 = e0123.z, E3 = e0123.w;
            unsigned E4 = e45.x,  E5 = e45.y;
            unsigned O0 = oddpair(E0, E1);
            unsigned O1 = oddpair(E1, E2);
            unsigned O2 = oddpair(E2, E3);
            unsigned O3 = oddpair(E3, E4);
            unsigned O4 = oddpair(E4, E5);

            unsigned w;
            w  = wr[0 * K + dj];
            m0 = __viaddmin_s16x2(E0, w, m0);
            m1 = __viaddmin_s16x2(E1, w, m1);
            m2 = __viaddmin_s16x2(E2, w, m2);
            m3 = __viaddmin_s16x2(E3, w, m3);
            w  = wr[1 * K + dj];
            m0 = __viaddmin_s16x2(O0, w, m0);
            m1 = __viaddmin_s16x2(O1, w, m1);
            m2 = __viaddmin_s16x2(O2, w, m2);
            m3 = __viaddmin_s16x2(O3, w, m3);
            w  = wr[2 * K + dj];
            m0 = __viaddmin_s16x2(E1, w, m0);
            m1 = __viaddmin_s16x2(E2, w, m1);
            m2 = __viaddmin_s16x2(E3, w, m2);
            m3 = __viaddmin_s16x2(E4, w, m3);
            w  = wr[3 * K + dj];
            m0 = __viaddmin_s16x2(O1, w, m0);
            m1 = __viaddmin_s16x2(O2, w, m1);
            m2 = __viaddmin_s16x2(O3, w, m2);
            m3 = __viaddmin_s16x2(O4, w, m3);
            w  = wr[4 * K + dj];
            m0 = __viaddmin_s16x2(E2, w, m0);
            m1 = __viaddmin_s16x2(E3, w, m1);
            m2 = __viaddmin_s16x2(E4, w, m2);
            m3 = __viaddmin_s16x2(E5, w, m3);
        }

        const int gi = tile_y + ty * 8;
        float* op = out + ((size_t)bo * H + gi) * W + tile_x + lc;
        op[0 * W] = lo16(m0) * INVMID;
        op[1 * W] = hi16(m0) * INVMID;
        op[2 * W] = lo16(m1) * INVMID;
        op[3 * W] = hi16(m1) * INVMID;
        op[4 * W] = lo16(m2) * INVMID;
        op[5 * W] = hi16(m2) * INVMID;
        op[6 * W] = lo16(m3) * INVMID;
        op[7 * W] = hi16(m3) * INVMID;
    }
}

// ---------------------------------------------------------------------------
extern "C" void kernel_launch(void* const* d_in, const int* in_sizes, int n_in,
                              void* d_out, int out_size) {
    const float* x  = (const float*)d_in[0];
    const float* wd = (const float*)d_in[1];
    const float* we = (const float*)d_in[2];
    float*       out = (float*)d_out;

    dim3 bD(32, 16);
    dim3 gD(W / DT_W, H / DT_H, B);          // 8 x 8 x 4 = 256 blocks x 512 thr
    dilate_kernel<<<gD, bD>>>(x, wd);

    dim3 bE(32, 8);
    dim3 gE(W / ER_TW, H / ER_TH, B * COUT); // 4 x 4 x 64 = 1024 blocks
    erode_kernel<<<gE, bE>>>(we, out);
}